// round 1
// baseline (speedup 1.0000x reference)
#include <cuda_runtime.h>

// Shapes (fixed by the problem)
//   x: (176, 64, 56, 56) f32
//   y: (176, 128, 28, 28) f32
//   out: (176, 192, 56, 56) f32 = concat(x, upsample2x(y)) on channels
namespace cfg {
constexpr int B  = 176;
constexpr int C1 = 64;
constexpr int C2 = 128;
constexpr int H1 = 56;
constexpr int W1 = 56;
constexpr int H2 = 28;
constexpr int W2 = 28;
constexpr int CO = C1 + C2;            // 192
constexpr int HW1 = H1 * W1;           // 3136
constexpr int HW2 = H2 * W2;           // 784

// float4 counts
constexpr int X_F4_PER_B   = C1 * HW1 / 4;   // 50176
constexpr int OUT_F4_PER_B = CO * HW1 / 4;   // 150528
constexpr int W1_F4        = W1 / 4;         // 14
constexpr long long N_XCOPY = (long long)B * X_F4_PER_B;            // 8,830,976
constexpr long long N_YUP   = (long long)B * C2 * H1 * W1_F4;      // 17,661,952
}

// Kernel 1: copy x into out channels [0, 64). Pure float4 memcpy with a
// per-batch output stride remap.
__global__ void __launch_bounds__(256) xcopy_kernel(const float4* __restrict__ x,
                                                    float4* __restrict__ out) {
    long long i = (long long)blockIdx.x * blockDim.x + threadIdx.x;
    if (i >= cfg::N_XCOPY) return;
    int b = (int)(i / cfg::X_F4_PER_B);
    int r = (int)(i - (long long)b * cfg::X_F4_PER_B);
    out[(long long)b * cfg::OUT_F4_PER_B + r] = x[i];
}

// Kernel 2: nearest-neighbor 2x upsample of y into out channels [64, 192).
// One thread = one output float4 (4 consecutive w). Source = one aligned
// float2 (2 consecutive y values), duplicated per-lane.
__global__ void __launch_bounds__(256) yup_kernel(const float2* __restrict__ y2,
                                                  float4* __restrict__ out) {
    long long i = (long long)blockIdx.x * blockDim.x + threadIdx.x;
    if (i >= cfg::N_YUP) return;

    // i = (((b*C2 + c)*H1 + h)*W1_F4 + w4)
    int w4 = (int)(i % cfg::W1_F4);
    long long t = i / cfg::W1_F4;
    int h = (int)(t % cfg::H1);
    t /= cfg::H1;
    int c = (int)(t % cfg::C2);
    int b = (int)(t / cfg::C2);

    // y element row: (b, c, h/2, :) ; float2 index within row = w4
    long long y2_idx = (((long long)b * cfg::C2 + c) * cfg::H2 + (h >> 1)) * (cfg::W2 / 2) + w4;
    float2 v = y2[y2_idx];

    float4 o;
    o.x = v.x; o.y = v.x;
    o.z = v.y; o.w = v.y;

    long long o_idx = (long long)b * cfg::OUT_F4_PER_B
                    + (long long)(cfg::C1 + c) * (cfg::HW1 / 4)
                    + (long long)h * cfg::W1_F4 + w4;
    out[o_idx] = o;
}

extern "C" void kernel_launch(void* const* d_in, const int* in_sizes, int n_in,
                              void* d_out, int out_size) {
    const float4* x  = (const float4*)d_in[0];
    const float2* y2 = (const float2*)d_in[1];
    float4* out = (float4*)d_out;

    constexpr int T = 256;
    long long gx = (cfg::N_XCOPY + T - 1) / T;
    long long gy = (cfg::N_YUP   + T - 1) / T;

    xcopy_kernel<<<(unsigned)gx, T>>>(x, out);
    yup_kernel<<<(unsigned)gy, T>>>(y2, out);
}

// round 2
// speedup vs baseline: 1.1880x; 1.1880x over previous
#include <cuda_runtime.h>

// Shapes (fixed):
//   x:   (176, 64, 56, 56) f32
//   y:   (176, 128, 28, 28) f32
//   out: (176, 192, 56, 56) f32 = concat(x, nearest_upsample2x(y)) on channels
namespace cfg {
constexpr int B  = 176;
constexpr int C1 = 64;
constexpr int C2 = 128;
constexpr int H1 = 56;
constexpr int W1 = 56;
constexpr int H2 = 28;

constexpr int HW1_F4       = H1 * W1 / 4;        // 784 float4 per (b,c) plane in out
constexpr int X_F4_PER_B   = C1 * HW1_F4;        // 50176
constexpr int OUT_F4_PER_B = (C1 + C2) * HW1_F4; // 150528
constexpr int W1_F4        = W1 / 4;             // 14  (also = W2/2 float2 per y row)

constexpr int N_XCOPY = B * X_F4_PER_B;          // 8,830,976 float4
// yup: one thread per y float2 = per (b, c, h2, w4): 176*128*28*14
constexpr int N_YUP   = B * C2 * H2 * W1_F4;     // 8,830,976 threads

constexpr int T = 256;
constexpr int XBLK = N_XCOPY / T;                // 34,496 (exact)
constexpr int YBLK = N_YUP / T;                  // 34,496 (exact)
}

__global__ void __launch_bounds__(cfg::T) fused_concat_upsample(
    const float4* __restrict__ x,
    const float2* __restrict__ y2,
    float4* __restrict__ out)
{
    int bid = blockIdx.x;
    if (bid < cfg::XBLK) {
        // ---- x copy: out channels [0,64) ----
        int i = bid * cfg::T + threadIdx.x;            // < 8.8M, fits int
        int b = i / cfg::X_F4_PER_B;
        int r = i - b * cfg::X_F4_PER_B;
        out[b * cfg::OUT_F4_PER_B + r] = x[i];
    } else {
        // ---- y nearest-2x upsample: out channels [64,192) ----
        int i = (bid - cfg::XBLK) * cfg::T + threadIdx.x;
        // i = ((b*C2 + c)*H2 + h2)*14 + w4  — which is EXACTLY the y2 index.
        float2 v = y2[i];

        int w4 = i % cfg::W1_F4;
        int t  = i / cfg::W1_F4;                       // (b*C2+c)*H2 + h2
        int h2 = t % cfg::H2;
        int bc = t / cfg::H2;                          // b*C2 + c
        int c  = bc % cfg::C2;
        int b  = bc / cfg::C2;

        float4 o;
        o.x = v.x; o.y = v.x;
        o.z = v.y; o.w = v.y;

        int obase = b * cfg::OUT_F4_PER_B
                  + (cfg::C1 + c) * cfg::HW1_F4
                  + (2 * h2) * cfg::W1_F4 + w4;
        out[obase] = o;                 // row 2*h2
        out[obase + cfg::W1_F4] = o;    // row 2*h2 + 1
    }
}

extern "C" void kernel_launch(void* const* d_in, const int* in_sizes, int n_in,
                              void* d_out, int out_size) {
    const float4* x  = (const float4*)d_in[0];
    const float2* y2 = (const float2*)d_in[1];
    float4* out = (float4*)d_out;

    fused_concat_upsample<<<cfg::XBLK + cfg::YBLK, cfg::T>>>(x, y2, out);
}